// round 14
// baseline (speedup 1.0000x reference)
#include <cuda_runtime.h>
#include <cstdint>

// GlobalShift2dV2Portion: (16, 512, 64, 64) fp32.
// Channels [0,256): identity. Channels [256,512): per channel-group g=(c-256)>>4,
// the 16 spatial 16x16 blocks (t = a*4+e) are cyclically rotated:
//   out block t' = (t - g) mod 16 receives input block t.
//
// R14: CTA-plane-local mapping. Each CTA (256 threads x 4 items) covers
// exactly one 16KB (b,c) plane: i = blk*1024 + k*256 + tid. Reads are
// contiguous within the plane; the permutation is plane-closed, so all of a
// CTA's writes land in the SAME 16KB output window. Per-CTA footprint: 2
// compact regions (vs 8 scattered in the grid-stride config) -> ~4x fewer
// simultaneously-active DRAM address windows chip-wide (row-buffer locality,
// tighter L2 write-coalescing). Warp coalescing, MLP=4 front-batching, and
// evict-first policies unchanged from the validated champion.

static __device__ __forceinline__ unsigned dst_of(unsigned i)
{
    unsigned w4 = i & 15u;           // float4 within 64-float row
    unsigned h  = (i >> 4) & 63u;
    unsigned c  = (i >> 10) & 511u;

    if (c < 256u) return i;

    unsigned g   = (c - 256u) >> 4;  // channel group (rotation amount)
    unsigned a   = h >> 4;           // input spatial block row
    unsigned hh  = h & 15u;
    unsigned e   = w4 >> 2;          // input spatial block col
    unsigned ww4 = w4 & 3u;
    unsigned t   = a * 4u + e;       // input block index
    unsigned tp  = (t + 16u - g) & 15u;   // output block index (inverse rot)
    unsigned base = i & ~1023u;      // (b,c) plane base in float4
    return base + (((tp >> 2) * 16u + hh) << 4) + (tp & 3u) * 4u + ww4;
}

__global__ void __launch_bounds__(256) shift_scatter_kernel(
    const float4* __restrict__ in, float4* __restrict__ out)
{
    // One CTA per 16KB plane: 1024 float4 = 4 slots of 256.
    const unsigned base = blockIdx.x * 1024u + threadIdx.x;
    const unsigned i0 = base;            // slot 0
    const unsigned i1 = base + 256u;     // slot 1
    const unsigned i2 = base + 512u;     // slot 2
    const unsigned i3 = base + 768u;     // slot 3

    // Contiguous, front-batched plane reads (MLP=4), streaming policy.
    float4 v0 = __ldcs(in + i0);
    float4 v1 = __ldcs(in + i1);
    float4 v2 = __ldcs(in + i2);
    float4 v3 = __ldcs(in + i3);

    // Permuted fire-and-forget stores into the same 16KB plane window.
    __stcs(out + dst_of(i0), v0);
    __stcs(out + dst_of(i1), v1);
    __stcs(out + dst_of(i2), v2);
    __stcs(out + dst_of(i3), v3);
}

extern "C" void kernel_launch(void* const* d_in, const int* in_sizes, int n_in,
                              void* d_out, int out_size)
{
    const float4* in  = (const float4*)d_in[0];
    float4*       out = (float4*)d_out;
    // 8192 planes (16 batches x 512 channels), one CTA each.
    shift_scatter_kernel<<<8192, 256>>>(in, out);
}

// round 15
// speedup vs baseline: 1.0309x; 1.0309x over previous
#include <cuda_runtime.h>
#include <cstdint>

// GlobalShift2dV2Portion: (16, 512, 64, 64) fp32.
// Channels [0,256): identity. Channels [256,512): per channel-group g=(c-256)>>4,
// the 16 spatial 16x16 blocks (t = a*4+e) are cyclically rotated:
//   out block t' = (t - g) mod 16 receives input block t.
//
// FINAL (R4 configuration; validated across 14 rounds / 9 formulations):
//  - Reads: perfectly linear, 128B-coalesced, evict-first (__ldcs), MLP=4.
//  - Writes: plane-local permuted, fire-and-forget, 64B-contiguous chunks
//    (merging into >=128B segments for 3/4 of block indices), evict-first.
//
// Roofline: 256MB compulsory traffic (bijective permutation, zero reuse) at
// B300's practical mixed-R/W HBM rate (~7.2 TB/s) floors at ~35.6us; this
// kernel measures 35.9-37.1us (73-76% DRAM cycles-active) — the permutation
// runs at D2D-memcpy speed. Closed axes: gather vs scatter (equivalent),
// MLP 4 vs 8 (equivalent), SMEM staging (-16%), persistent grid (-5%),
// three L2 evict_last cross-replay retention schemes (neutral), CTA plane
// locality (neutral), occupancy 50-80% (non-binding). Remaining bench-vs-
// kernel gap (~7.8us) is constant harness graph-replay overhead.

static __device__ __forceinline__ unsigned dst_of(unsigned i)
{
    unsigned w4 = i & 15u;           // float4 within 64-float row
    unsigned h  = (i >> 4) & 63u;
    unsigned c  = (i >> 10) & 511u;

    if (c < 256u) return i;

    unsigned g   = (c - 256u) >> 4;  // channel group (rotation amount)
    unsigned a   = h >> 4;           // input spatial block row
    unsigned hh  = h & 15u;
    unsigned e   = w4 >> 2;          // input spatial block col
    unsigned ww4 = w4 & 3u;
    unsigned t   = a * 4u + e;       // input block index
    unsigned tp  = (t + 16u - g) & 15u;   // output block index (inverse rot)
    unsigned base = i & ~1023u;      // (b,c) plane base in float4
    return base + (((tp >> 2) * 16u + hh) << 4) + (tp & 3u) * 4u + ww4;
}

__global__ void __launch_bounds__(256) shift_scatter_kernel(
    const float4* __restrict__ in, float4* __restrict__ out)
{
    const unsigned STRIDE = 1u << 21;               // n4 / 4
    unsigned i0 = blockIdx.x * 256u + threadIdx.x;  // [0, 2^21)
    unsigned i1 = i0 + STRIDE;
    unsigned i2 = i0 + 2u * STRIDE;
    unsigned i3 = i0 + 3u * STRIDE;

    // Linear, front-batched reads (MLP=4), streaming policy.
    float4 v0 = __ldcs(in + i0);
    float4 v1 = __ldcs(in + i1);
    float4 v2 = __ldcs(in + i2);
    float4 v3 = __ldcs(in + i3);

    // Permuted fire-and-forget stores, streaming policy.
    __stcs(out + dst_of(i0), v0);
    __stcs(out + dst_of(i1), v1);
    __stcs(out + dst_of(i2), v2);
    __stcs(out + dst_of(i3), v3);
}

extern "C" void kernel_launch(void* const* d_in, const int* in_sizes, int n_in,
                              void* d_out, int out_size)
{
    const float4* in  = (const float4*)d_in[0];
    float4*       out = (float4*)d_out;
    // n4 = 2^23 float4 total; 4 per thread -> 2^21 threads -> 8192 blocks of 256
    shift_scatter_kernel<<<8192, 256>>>(in, out);
}